// round 10
// baseline (speedup 1.0000x reference)
#include <cuda_runtime.h>
#include <cstdint>

#define BATCH 1024
#define SEQL  200
#define DIM   128

// Scratch (allocation-free rule: __device__ globals)
__device__ float xh0_buf[BATCH * DIM];   // g hi
__device__ float xl0_buf[BATCH * DIM];   // g lo
__device__ float xh1_buf[BATCH * DIM];   // ag hi
__device__ float xl1_buf[BATCH * DIM];   // ag lo
__device__ float part_buf[4 * BATCH * DIM];  // 4 K-split partials (2 MB)

// ---------------------------------------------------------------------------
// tf32 helpers
// ---------------------------------------------------------------------------
__device__ __forceinline__ unsigned tf32_rna(float x) {
    unsigned r; asm("cvt.rna.tf32.f32 %0, %1;" : "=r"(r) : "f"(x)); return r;
}
// split x into hi (tf32 value in fp32 container) and lo (tf32 of remainder)
__device__ __forceinline__ void tf32_split(float x, float& hi, float& lo) {
    unsigned h = tf32_rna(x);
    hi = __uint_as_float(h);
    lo = __uint_as_float(tf32_rna(x - hi));
}
__device__ __forceinline__ void mma_tf32(float c[4],
                                         const unsigned a[4],
                                         unsigned b0, unsigned b1) {
    asm volatile(
        "mma.sync.aligned.m16n8k8.row.col.f32.tf32.tf32.f32 "
        "{%0,%1,%2,%3}, {%4,%5,%6,%7}, {%8,%9}, {%0,%1,%2,%3};"
        : "+f"(c[0]), "+f"(c[1]), "+f"(c[2]), "+f"(c[3])
        : "r"(a[0]), "r"(a[1]), "r"(a[2]), "r"(a[3]), "r"(b0), "r"(b1));
}

// ---------------------------------------------------------------------------
// Kernel 1: g[b] = sum_l item_embedding[items[b,l]]; writes tf32 hi/lo split.
// (DRAM-saturated random gather: ~86 MB compulsory @ ~3.9 TB/s.)
// ---------------------------------------------------------------------------
__global__ void __launch_bounds__(256) gather_sum_kernel(
    const float* __restrict__ emb,
    const void* __restrict__ items_raw,
    float* __restrict__ ghi, float* __restrict__ glo)
{
    const int b    = blockIdx.x;
    const int t    = threadIdx.x;
    const int w    = t >> 5;
    const int lane = t & 31;

    __shared__ int sidx[SEQL];
    __shared__ int mode64;
    __shared__ float4 spart[8][32];

    if (t == 0) {
        // int64 storage => odd int32 words of first 16 elements are all zero
        const int* p = (const int*)items_raw;
        int ok = 1;
        #pragma unroll
        for (int i = 0; i < 16; i++) ok &= (p[2 * i + 1] == 0);
        mode64 = ok;
    }
    __syncthreads();

    if (t < SEQL) {
        if (mode64) sidx[t] = (int)((const long long*)items_raw)[(long long)b * SEQL + t];
        else        sidx[t] = ((const int*)items_raw)[b * SEQL + t];
    }
    __syncthreads();

    float4 acc[5], v[5];
    #pragma unroll
    for (int j = 0; j < 5; j++) acc[j] = make_float4(0.f, 0.f, 0.f, 0.f);

    #pragma unroll
    for (int j = 0; j < 5; j++)
        v[j] = *(const float4*)&emb[(size_t)sidx[w + 8 * j] * DIM + lane * 4];

    #pragma unroll
    for (int s = 0; s < 5; s++) {
        float4 nv[5];
        if (s < 4) {
            #pragma unroll
            for (int j = 0; j < 5; j++)
                nv[j] = *(const float4*)&emb[(size_t)sidx[w + 8 * (5 * (s + 1) + j)] * DIM + lane * 4];
        }
        #pragma unroll
        for (int j = 0; j < 5; j++) {
            acc[j].x += v[j].x; acc[j].y += v[j].y;
            acc[j].z += v[j].z; acc[j].w += v[j].w;
        }
        if (s < 4) {
            #pragma unroll
            for (int j = 0; j < 5; j++) v[j] = nv[j];
        }
    }

    float4 s4;
    s4.x = ((acc[0].x + acc[1].x) + (acc[2].x + acc[3].x)) + acc[4].x;
    s4.y = ((acc[0].y + acc[1].y) + (acc[2].y + acc[3].y)) + acc[4].y;
    s4.z = ((acc[0].z + acc[1].z) + (acc[2].z + acc[3].z)) + acc[4].z;
    s4.w = ((acc[0].w + acc[1].w) + (acc[2].w + acc[3].w)) + acc[4].w;

    spart[w][lane] = s4;
    __syncthreads();
    if (w < 4) {
        float4 a = spart[w][lane], c = spart[w + 4][lane];
        a.x += c.x; a.y += c.y; a.z += c.z; a.w += c.w;
        spart[w][lane] = a;
    }
    __syncthreads();
    if (w < 2) {
        float4 a = spart[w][lane], c = spart[w + 2][lane];
        a.x += c.x; a.y += c.y; a.z += c.z; a.w += c.w;
        spart[w][lane] = a;
    }
    __syncthreads();
    if (w == 0) {
        float4 a = spart[0][lane], c = spart[1][lane];
        a.x += c.x; a.y += c.y; a.z += c.z; a.w += c.w;
        float4 h4, l4;
        tf32_split(a.x, h4.x, l4.x);
        tf32_split(a.y, h4.y, l4.y);
        tf32_split(a.z, h4.z, l4.z);
        tf32_split(a.w, h4.w, l4.w);
        *(float4*)&ghi[b * DIM + lane * 4] = h4;
        *(float4*)&glo[b * DIM + lane * 4] = l4;
    }
}

// ---------------------------------------------------------------------------
// Kernel 2: tensor-core 3xTF32 GEMM partial:
//   part[split][m][n] (+)= A[m, k0:k0+256] @ X[k0:k0+256, n]
// grid = 128 blocks (32 row-groups of BM=32  x  4 K-splits), 256 threads.
// Per warp: 2 m16 tiles x 2 n8 tiles; mma.sync.m16n8k8.tf32, 3 products
// (hh, hl, lh) per tile per k-step. A staged fp32 in smem, split in regs;
// X pre-split (hi/lo) in gmem, B-fragments loaded straight from L2.
// ---------------------------------------------------------------------------
__global__ void __launch_bounds__(256) gemm_tc_kernel(
    const float* __restrict__ A,
    const float* __restrict__ Xhi,
    const float* __restrict__ Xlo,
    float* __restrict__ part)
{
    const int mg    = blockIdx.x >> 2;   // 0..31: 32-row group
    const int split = blockIdx.x & 3;    // 0..3 : K quarter
    const int k0 = split * 256;
    const int m0 = mg * 32;

    __shared__ __align__(16) float sA[32][260];   // 32x256 fp32, pad 4

    // ---- stage A [32][256] (coalesced float4 loads) ----
    {
        const int row = threadIdx.x >> 3;   // 32 rows, 8 threads/row
        const int cb  = threadIdx.x & 7;
        const float* ar = A + (size_t)(m0 + row) * 1024 + k0;
        #pragma unroll
        for (int j = 0; j < 8; j++) {
            const int c4 = cb + j * 8;      // float4 index 0..63
            const float4 v = *(const float4*)&ar[c4 * 4];
            *(float4*)&sA[row][c4 * 4] = v;
        }
    }
    __syncthreads();

    const int lane = threadIdx.x & 31;
    const int warp = threadIdx.x >> 5;   // 0..7
    const int gid  = lane >> 2;          // 0..7
    const int tig  = lane & 3;           // 0..3
    const int nb   = warp * 16;          // warp's 16-col slice

    float acc[2][2][4];
    #pragma unroll
    for (int mt = 0; mt < 2; mt++)
        #pragma unroll
        for (int nt = 0; nt < 2; nt++)
            #pragma unroll
            for (int i = 0; i < 4; i++) acc[mt][nt][i] = 0.f;

    #pragma unroll 1
    for (int ks = 0; ks < 32; ks++) {
        const int kk = ks * 8;

        // A fragments (both m16 tiles), split hi/lo in registers
        unsigned ah[2][4], al[2][4];
        #pragma unroll
        for (int mt = 0; mt < 2; mt++) {
            const int r0 = mt * 16 + gid;
            const float f0 = sA[r0][kk + tig];
            const float f1 = sA[r0 + 8][kk + tig];
            const float f2 = sA[r0][kk + tig + 4];
            const float f3 = sA[r0 + 8][kk + tig + 4];
            float h, l;
            tf32_split(f0, h, l); ah[mt][0] = __float_as_uint(h); al[mt][0] = __float_as_uint(l);
            tf32_split(f1, h, l); ah[mt][1] = __float_as_uint(h); al[mt][1] = __float_as_uint(l);
            tf32_split(f2, h, l); ah[mt][2] = __float_as_uint(h); al[mt][2] = __float_as_uint(l);
            tf32_split(f3, h, l); ah[mt][3] = __float_as_uint(h); al[mt][3] = __float_as_uint(l);
        }

        // B fragments per n-tile (X already tf32-valued hi/lo in gmem)
        #pragma unroll
        for (int nt = 0; nt < 2; nt++) {
            const int n    = nb + nt * 8 + gid;
            const int krow = k0 + kk + tig;
            const unsigned bh0 = __float_as_uint(Xhi[krow * DIM + n]);
            const unsigned bh1 = __float_as_uint(Xhi[(krow + 4) * DIM + n]);
            const unsigned bl0 = __float_as_uint(Xlo[krow * DIM + n]);
            const unsigned bl1 = __float_as_uint(Xlo[(krow + 4) * DIM + n]);
            #pragma unroll
            for (int mt = 0; mt < 2; mt++) {
                mma_tf32(acc[mt][nt], ah[mt], bh0, bh1);   // hi*hi
                mma_tf32(acc[mt][nt], ah[mt], bl0, bl1);   // hi*lo
                mma_tf32(acc[mt][nt], al[mt], bh0, bh1);   // lo*hi
            }
        }
    }

    // ---- write partials: part[split][m][n] ----
    float* pbase = part + (size_t)split * BATCH * DIM;
    #pragma unroll
    for (int mt = 0; mt < 2; mt++) {
        const int r = m0 + mt * 16 + gid;
        #pragma unroll
        for (int nt = 0; nt < 2; nt++) {
            const int n = nb + nt * 8 + 2 * tig;
            pbase[r * DIM + n]           = acc[mt][nt][0];
            pbase[r * DIM + n + 1]       = acc[mt][nt][1];
            pbase[(r + 8) * DIM + n]     = acc[mt][nt][2];
            pbase[(r + 8) * DIM + n + 1] = acc[mt][nt][3];
        }
    }
}

// ---------------------------------------------------------------------------
// Kernel 3: reduce 4 K-split partials.
//  MODE 0: re-split result to tf32 hi/lo (feeds next GEMM).
//  MODE 1: fused selu + row L2-normalize -> final output.
// grid = 1024 (rows), 128 threads (cols).
// ---------------------------------------------------------------------------
template <int MODE>
__global__ void __launch_bounds__(128) reduce_kernel(
    const float* __restrict__ part,
    float* __restrict__ outA, float* __restrict__ outB)
{
    const int m = blockIdx.x;
    const int n = threadIdx.x;

    float s = 0.f;
    #pragma unroll
    for (int sp = 0; sp < 4; sp++)
        s += part[((size_t)sp * BATCH + m) * DIM + n];

    if (MODE == 0) {
        float h, l;
        tf32_split(s, h, l);
        outA[m * DIM + n] = h;
        outB[m * DIM + n] = l;
    } else {
        const float SELU_SCALE = 1.0507009873554804934f;
        const float SELU_ALPHA = 1.6732632423543772848f;
        const float sv = (s > 0.f) ? SELU_SCALE * s
                                   : SELU_SCALE * SELU_ALPHA * (expf(s) - 1.f);
        float sq = sv * sv;
        #pragma unroll
        for (int o = 16; o; o >>= 1) sq += __shfl_xor_sync(0xFFFFFFFFu, sq, o);
        __shared__ float ws[4];
        if ((n & 31) == 0) ws[n >> 5] = sq;
        __syncthreads();
        const float tot = ws[0] + ws[1] + ws[2] + ws[3];
        outA[m * DIM + n] = sv * rsqrtf(tot);
    }
}

// ---------------------------------------------------------------------------
// Launch: gather(+split) -> TC-GEMM(A) -> reduce+split -> TC-GEMM(D)
//         -> reduce+selu+norm
// (attention/entmax path is analytically identity on g: scores constant
//  along L, entmax of a constant is uniform, sum(p)*g = g)
// ---------------------------------------------------------------------------
extern "C" void kernel_launch(void* const* d_in, const int* in_sizes, int n_in,
                              void* d_out, int out_size)
{
    const float* emb   = (const float*)d_in[0];  // [500000, 128]
    const void*  items = d_in[1];                // [1024, 200] int64/int32
    const float* Amat  = (const float*)d_in[2];  // [1024, 1024]
    const float* Dmat  = (const float*)d_in[3];  // [1024, 1024]
    float* out = (float*)d_out;                  // [1024, 128]

    float *xh0, *xl0, *xh1, *xl1, *part;
    cudaGetSymbolAddress((void**)&xh0, xh0_buf);
    cudaGetSymbolAddress((void**)&xl0, xl0_buf);
    cudaGetSymbolAddress((void**)&xh1, xh1_buf);
    cudaGetSymbolAddress((void**)&xl1, xl1_buf);
    cudaGetSymbolAddress((void**)&part, part_buf);

    gather_sum_kernel<<<BATCH, 256>>>(emb, items, xh0, xl0);

    gemm_tc_kernel<<<128, 256>>>(Amat, xh0, xl0, part);     // part = A@g (4 splits)
    reduce_kernel<0><<<BATCH, DIM>>>(part, xh1, xl1);       // ag -> hi/lo

    gemm_tc_kernel<<<128, 256>>>(Dmat, xh1, xl1, part);     // part = D@ag
    reduce_kernel<1><<<BATCH, DIM>>>(part, out, nullptr);   // selu + norm
}

// round 11
// speedup vs baseline: 1.3706x; 1.3706x over previous
#include <cuda_runtime.h>
#include <cstdint>

#define BATCH 1024
#define SEQL  200
#define DIM   128

// Scratch (allocation-free rule: __device__ globals)
// Xf layout: [128 global ksteps][128 n][4 tig] float4 = {hi_k, lo_k, hi_k+4, lo_k+4}
// where k = kstep*8 + tig (k is the GEMM reduction index = row of X).
__device__ float xf0_buf[128 * 128 * 16];          // g   (1 MB)
__device__ float xf1_buf[128 * 128 * 16];          // ag  (1 MB)
__device__ float part_buf[4 * BATCH * DIM];        // 4 K-split partials (2 MB)

// ---------------------------------------------------------------------------
// tf32 helpers
// ---------------------------------------------------------------------------
__device__ __forceinline__ unsigned tf32_rna(float x) {
    unsigned r; asm("cvt.rna.tf32.f32 %0, %1;" : "=r"(r) : "f"(x)); return r;
}
__device__ __forceinline__ void tf32_split(float x, float& hi, float& lo) {
    unsigned h = tf32_rna(x);
    hi = __uint_as_float(h);
    lo = __uint_as_float(tf32_rna(x - hi));
}
__device__ __forceinline__ void mma_tf32(float c[4],
                                         const unsigned a[4],
                                         unsigned b0, unsigned b1) {
    asm volatile(
        "mma.sync.aligned.m16n8k8.row.col.f32.tf32.tf32.f32 "
        "{%0,%1,%2,%3}, {%4,%5,%6,%7}, {%8,%9}, {%0,%1,%2,%3};"
        : "+f"(c[0]), "+f"(c[1]), "+f"(c[2]), "+f"(c[3])
        : "r"(a[0]), "r"(a[1]), "r"(a[2]), "r"(a[3]), "r"(b0), "r"(b1));
}
__device__ __forceinline__ unsigned fu(float x) { return __float_as_uint(x); }

// Write one split value into the Xf fragment layout.
__device__ __forceinline__ void xf_write(float* xf, int k, int n, float v) {
    const int ksg = k >> 3;
    const int r7  = k & 7;
    const int tig = r7 & 3;
    const int off = (r7 < 4) ? 0 : 2;
    float h, l; tf32_split(v, h, l);
    *(float2*)&xf[(((ksg * 128 + n) * 4 + tig) << 2) + off] = make_float2(h, l);
}

// ---------------------------------------------------------------------------
// Kernel 1: g[b] = sum_l item_embedding[items[b,l]]; writes Xf frag layout.
// (DRAM-saturated random gather: ~86 MB compulsory @ ~3.9-4 TB/s.)
// ---------------------------------------------------------------------------
__global__ void __launch_bounds__(256) gather_sum_kernel(
    const float* __restrict__ emb,
    const void* __restrict__ items_raw,
    float* __restrict__ xf)
{
    const int b    = blockIdx.x;
    const int t    = threadIdx.x;
    const int w    = t >> 5;
    const int lane = t & 31;

    __shared__ int sidx[SEQL];
    __shared__ int mode64;
    __shared__ float4 spart[8][32];

    if (t == 0) {
        // int64 storage => odd int32 words of first 16 elements are all zero
        const int* p = (const int*)items_raw;
        int ok = 1;
        #pragma unroll
        for (int i = 0; i < 16; i++) ok &= (p[2 * i + 1] == 0);
        mode64 = ok;
    }
    __syncthreads();

    if (t < SEQL) {
        if (mode64) sidx[t] = (int)((const long long*)items_raw)[(long long)b * SEQL + t];
        else        sidx[t] = ((const int*)items_raw)[b * SEQL + t];
    }
    __syncthreads();

    float4 acc[5], v[5];
    #pragma unroll
    for (int j = 0; j < 5; j++) acc[j] = make_float4(0.f, 0.f, 0.f, 0.f);

    #pragma unroll
    for (int j = 0; j < 5; j++)
        v[j] = *(const float4*)&emb[(size_t)sidx[w + 8 * j] * DIM + lane * 4];

    #pragma unroll
    for (int s = 0; s < 5; s++) {
        float4 nv[5];
        if (s < 4) {
            #pragma unroll
            for (int j = 0; j < 5; j++)
                nv[j] = *(const float4*)&emb[(size_t)sidx[w + 8 * (5 * (s + 1) + j)] * DIM + lane * 4];
        }
        #pragma unroll
        for (int j = 0; j < 5; j++) {
            acc[j].x += v[j].x; acc[j].y += v[j].y;
            acc[j].z += v[j].z; acc[j].w += v[j].w;
        }
        if (s < 4) {
            #pragma unroll
            for (int j = 0; j < 5; j++) v[j] = nv[j];
        }
    }

    float4 s4;
    s4.x = ((acc[0].x + acc[1].x) + (acc[2].x + acc[3].x)) + acc[4].x;
    s4.y = ((acc[0].y + acc[1].y) + (acc[2].y + acc[3].y)) + acc[4].y;
    s4.z = ((acc[0].z + acc[1].z) + (acc[2].z + acc[3].z)) + acc[4].z;
    s4.w = ((acc[0].w + acc[1].w) + (acc[2].w + acc[3].w)) + acc[4].w;

    spart[w][lane] = s4;
    __syncthreads();
    if (w < 4) {
        float4 a = spart[w][lane], c = spart[w + 4][lane];
        a.x += c.x; a.y += c.y; a.z += c.z; a.w += c.w;
        spart[w][lane] = a;
    }
    __syncthreads();
    if (w < 2) {
        float4 a = spart[w][lane], c = spart[w + 2][lane];
        a.x += c.x; a.y += c.y; a.z += c.z; a.w += c.w;
        spart[w][lane] = a;
    }
    __syncthreads();
    if (w == 0) {
        float4 a = spart[0][lane], c = spart[1][lane];
        a.x += c.x; a.y += c.y; a.z += c.z; a.w += c.w;
        float av[4] = {a.x, a.y, a.z, a.w};
        #pragma unroll
        for (int j = 0; j < 4; j++)
            xf_write(xf, b, lane * 4 + j, av[j]);
    }
}

// ---------------------------------------------------------------------------
// Kernel 2: tensor-core 3xTF32 GEMM partial:
//   part[split][m0:m0+16][:] (+)= A[m0:m0+16, k0:k0+256] @ X[k0:k0+256, :]
// grid = 256 blocks (64 m-groups of 16 x 4 K-splits), 256 threads (8 warps).
//
//  - Prologue: A slice loaded coalesced, tf32-split ONCE, stored in
//    fragment-ordered smem (sAfh/sAfl[ks][lane][4]; 16B lane stride ->
//    conflict-free LDS.128). Inner loop A cost = 2 LDS.128, zero cvt.
//  - B: X pre-arranged in gmem in fragment order -> 1 coalesced LDG.128
//    per nt per kstep, ring-prefetched 4 ksteps ahead (barrier-free loop).
//  - 3 separate accumulator sets (hh/hl/lh) -> no MMA RAW chains.
//  Fragment<->matrix mappings identical to the R10-verified kernel.
// ---------------------------------------------------------------------------
__global__ void __launch_bounds__(256) gemm_tc_kernel(
    const float* __restrict__ A,
    const float4* __restrict__ Xf,   // [128 ksteps][128 n][4 tig]
    float* __restrict__ part)
{
    const int mg    = blockIdx.x >> 2;   // 0..63
    const int split = blockIdx.x & 3;    // 0..3
    const int m0 = mg * 16;
    const int k0 = split * 256;

    __shared__ __align__(16) float sAfh[32][32][4];   // 16 KB
    __shared__ __align__(16) float sAfl[32][32][4];   // 16 KB

    // ---- prologue: load + split + fragment-arrange A[16][256] ----
    {
        const int r  = threadIdx.x >> 4;     // 0..15 row
        const int kb = threadIdx.x & 15;     // 16 k each
        const float* ar = A + (size_t)(m0 + r) * 1024 + k0 + kb * 16;
        const int gid8 = r & 7;
        const int ehi  = (r >= 8) ? 1 : 0;
        #pragma unroll
        for (int j4 = 0; j4 < 4; j4++) {
            const float4 vv = *(const float4*)&ar[j4 * 4];
            const float va[4] = {vv.x, vv.y, vv.z, vv.w};
            #pragma unroll
            for (int e = 0; e < 4; e++) {
                const int kq   = kb * 16 + j4 * 4 + e;   // 0..255
                const int ks   = kq >> 3;
                const int kt   = kq & 7;
                const int lane = gid8 * 4 + (kt & 3);
                const int elem = ehi + ((kt >= 4) ? 2 : 0);
                float h, l; tf32_split(va[e], h, l);
                sAfh[ks][lane][elem] = h;
                sAfl[ks][lane][elem] = l;
            }
        }
    }
    __syncthreads();

    const int lane = threadIdx.x & 31;
    const int warp = threadIdx.x >> 5;   // 0..7
    const int gid  = lane >> 2;
    const int tig  = lane & 3;
    const int nb   = warp * 16;

    float ahh[2][4], ahl[2][4], alh[2][4];
    #pragma unroll
    for (int nt = 0; nt < 2; nt++)
        #pragma unroll
        for (int i = 0; i < 4; i++) { ahh[nt][i] = 0.f; ahl[nt][i] = 0.f; alh[nt][i] = 0.f; }

    const float4* Xq = Xf + (size_t)(split * 32) * 128 * 4;
    const int n0 = nb + gid;
    const int n1 = nb + 8 + gid;

    // ring prefetch: 4 ksteps deep
    float4 br[4][2];
    #pragma unroll
    for (int q = 0; q < 4; q++) {
        br[q][0] = Xq[(q * 128 + n0) * 4 + tig];
        br[q][1] = Xq[(q * 128 + n1) * 4 + tig];
    }

    #pragma unroll 1
    for (int ksb = 0; ksb < 32; ksb += 4) {
        #pragma unroll
        for (int q = 0; q < 4; q++) {
            const int ks = ksb + q;
            const float4 h4 = *(const float4*)&sAfh[ks][lane][0];
            const float4 l4 = *(const float4*)&sAfl[ks][lane][0];
            const unsigned ah[4] = {fu(h4.x), fu(h4.y), fu(h4.z), fu(h4.w)};
            const unsigned al[4] = {fu(l4.x), fu(l4.y), fu(l4.z), fu(l4.w)};
            #pragma unroll
            for (int nt = 0; nt < 2; nt++) {
                const float4 b = br[q][nt];
                mma_tf32(ahh[nt], ah, fu(b.x), fu(b.z));   // hi*hi
                mma_tf32(ahl[nt], ah, fu(b.y), fu(b.w));   // hi*lo
                mma_tf32(alh[nt], al, fu(b.x), fu(b.z));   // lo*hi
            }
            if (ks + 4 < 32) {
                br[q][0] = Xq[((ks + 4) * 128 + n0) * 4 + tig];
                br[q][1] = Xq[((ks + 4) * 128 + n1) * 4 + tig];
            }
        }
    }

    // ---- epilogue: write partials (R10-verified C mapping) ----
    float* pb = part + (size_t)split * BATCH * DIM;
    const int r = m0 + gid;
    #pragma unroll
    for (int nt = 0; nt < 2; nt++) {
        const int n = nb + nt * 8 + 2 * tig;
        const float c0 = ahh[nt][0] + ahl[nt][0] + alh[nt][0];
        const float c1 = ahh[nt][1] + ahl[nt][1] + alh[nt][1];
        const float c2 = ahh[nt][2] + ahl[nt][2] + alh[nt][2];
        const float c3 = ahh[nt][3] + ahl[nt][3] + alh[nt][3];
        pb[r * DIM + n]           = c0;
        pb[r * DIM + n + 1]       = c1;
        pb[(r + 8) * DIM + n]     = c2;
        pb[(r + 8) * DIM + n + 1] = c3;
    }
}

// ---------------------------------------------------------------------------
// Kernel 3: reduce 4 K-split partials.
//  MODE 0: re-split to Xf fragment layout (feeds next GEMM).
//  MODE 1: fused selu + row L2-normalize -> final output.
// ---------------------------------------------------------------------------
template <int MODE>
__global__ void __launch_bounds__(128) reduce_kernel(
    const float* __restrict__ part,
    float* __restrict__ outv)
{
    const int m = blockIdx.x;
    const int n = threadIdx.x;

    float s = 0.f;
    #pragma unroll
    for (int sp = 0; sp < 4; sp++)
        s += part[((size_t)sp * BATCH + m) * DIM + n];

    if (MODE == 0) {
        xf_write(outv, m, n, s);
    } else {
        const float SELU_SCALE = 1.0507009873554804934f;
        const float SELU_ALPHA = 1.6732632423543772848f;
        const float sv = (s > 0.f) ? SELU_SCALE * s
                                   : SELU_SCALE * SELU_ALPHA * (expf(s) - 1.f);
        float sq = sv * sv;
        #pragma unroll
        for (int o = 16; o; o >>= 1) sq += __shfl_xor_sync(0xFFFFFFFFu, sq, o);
        __shared__ float ws[4];
        if ((n & 31) == 0) ws[n >> 5] = sq;
        __syncthreads();
        const float tot = ws[0] + ws[1] + ws[2] + ws[3];
        outv[m * DIM + n] = sv * rsqrtf(tot);
    }
}

// ---------------------------------------------------------------------------
// Launch: gather(->Xf) -> TC-GEMM(A) -> reduce(->Xf) -> TC-GEMM(D)
//         -> reduce+selu+norm
// (attention/entmax path is analytically identity on g: scores constant
//  along L, entmax of a constant is uniform, sum(p)*g = g)
// ---------------------------------------------------------------------------
extern "C" void kernel_launch(void* const* d_in, const int* in_sizes, int n_in,
                              void* d_out, int out_size)
{
    const float* emb   = (const float*)d_in[0];  // [500000, 128]
    const void*  items = d_in[1];                // [1024, 200] int64/int32
    const float* Amat  = (const float*)d_in[2];  // [1024, 1024]
    const float* Dmat  = (const float*)d_in[3];  // [1024, 1024]
    float* out = (float*)d_out;                  // [1024, 128]

    float *xf0, *xf1, *part;
    cudaGetSymbolAddress((void**)&xf0, xf0_buf);
    cudaGetSymbolAddress((void**)&xf1, xf1_buf);
    cudaGetSymbolAddress((void**)&part, part_buf);

    gather_sum_kernel<<<BATCH, 256>>>(emb, items, xf0);

    gemm_tc_kernel<<<256, 256>>>(Amat, (const float4*)xf0, part);  // A@g
    reduce_kernel<0><<<BATCH, DIM>>>(part, xf1);                   // -> Xf(ag)

    gemm_tc_kernel<<<256, 256>>>(Dmat, (const float4*)xf1, part);  // D@ag
    reduce_kernel<1><<<BATCH, DIM>>>(part, out);                   // selu+norm
}